// round 5
// baseline (speedup 1.0000x reference)
#include <cuda_runtime.h>
#include <cstdint>

#define KCODES   512
#define DDIM     64
#define HWSZ     4096
#define NPTS     131072
#define TPTS     128            // points per tile
#define NTILES   (NPTS / TPTS)  // 1024
#define ZQ_ELEMS 8388608

// dynamic SMEM layout (bytes):
//  s_cb : u64[64][256]  pair-transposed codebook {e[2p][c], e[2p+1][c]}  131072
//  s_z2 : u64[64][128]  duplicated z {v,v} per (channel, point)          65536
//  s_en : u64[256]      {||e_2p||^2, ||e_2p+1||^2}                       2048
//  s_zn : float[128]                                                     512
//  s_idx: int[128]                                                       512
#define OFF_CB   0
#define OFF_Z    131072
#define OFF_EN   (OFF_Z + 65536)
#define OFF_ZN   (OFF_EN + 2048)
#define OFF_IDX  (OFF_ZN + 512)
#define SMEM_BYTES (OFF_IDX + 512)   // 199680

__device__ __forceinline__ unsigned long long pk2(float lo, float hi) {
    unsigned long long r;
    asm("mov.b64 %0, {%1,%2};" : "=l"(r) : "f"(lo), "f"(hi));
    return r;
}
__device__ __forceinline__ float2 unpk2(unsigned long long v) {
    float2 f;
    asm("mov.b64 {%0,%1}, %2;" : "=f"(f.x), "=f"(f.y) : "l"(v));
    return f;
}
// packed dual-fp32 FMA (sm_100+; PTX-only, ptxas never auto-fuses)
__device__ __forceinline__ void ffma2(unsigned long long& d,
                                      unsigned long long a,
                                      unsigned long long b) {
    asm("fma.rn.f32x2 %0, %1, %2, %0;" : "+l"(d) : "l"(a), "l"(b));
}

// mode: 0 = z_q only; 1 = z_q + indices-as-float appended; 2 = indices only (int32)
__global__ void __launch_bounds__(256, 1)
vq_kernel(const float* __restrict__ z_e,
          const float* __restrict__ cb,
          float* __restrict__ out,
          int mode, int nctas)
{
    extern __shared__ char smem[];
    unsigned long long* s_cb = (unsigned long long*)(smem + OFF_CB);
    unsigned long long* s_z2 = (unsigned long long*)(smem + OFF_Z);
    unsigned long long* s_en = (unsigned long long*)(smem + OFF_EN);
    float* s_zn  = (float*)(smem + OFF_ZN);
    int*   s_idx = (int*)  (smem + OFF_IDX);

    const int tid = threadIdx.x;
    const int cg  = tid & 15;    // code group
    const int pg  = tid >> 4;    // point group: points pg*8 .. pg*8+7

    // ---- Stage codebook once: pair-transposed + per-code norms ----
    {
        const float4* e0 = (const float4*)(cb + (size_t)(2 * tid) * DDIM);
        float n0 = 0.f, n1 = 0.f;
        #pragma unroll
        for (int c4 = 0; c4 < 16; c4++) {
            float4 a = e0[c4];        // code 2t
            float4 b = e0[16 + c4];   // code 2t+1
            n0 += a.x*a.x + a.y*a.y + a.z*a.z + a.w*a.w;
            n1 += b.x*b.x + b.y*b.y + b.z*b.z + b.w*b.w;
            int c = 4 * c4;
            s_cb[(c+0)*256 + tid] = pk2(a.x, b.x);
            s_cb[(c+1)*256 + tid] = pk2(a.y, b.y);
            s_cb[(c+2)*256 + tid] = pk2(a.z, b.z);
            s_cb[(c+3)*256 + tid] = pk2(a.w, b.w);
        }
        s_en[tid] = pk2(n0, n1);
    }

    for (int tile = blockIdx.x; tile < NTILES; tile += nctas) {
        // ---- Stage z tile, duplicated {v,v}. Tile never straddles batch b. ----
        {
            const float* zg = z_e + (size_t)(tile >> 5) * (DDIM * HWSZ)
                                  + (size_t)(tile & 31) * TPTS;
            #pragma unroll
            for (int it = 0; it < 8; it++) {
                int i4 = it * 256 + tid;        // 0..2047 float4 slots
                int c  = i4 >> 5;               // channel
                int p  = (i4 & 31) * 4;         // point base
                float4 v = *(const float4*)(zg + (size_t)c * HWSZ + p);
                ulonglong2* dst = (ulonglong2*)(s_z2 + c * 128 + p);
                dst[0] = make_ulonglong2(pk2(v.x, v.x), pk2(v.y, v.y));
                dst[1] = make_ulonglong2(pk2(v.z, v.z), pk2(v.w, v.w));
            }
        }
        __syncthreads();

        // ---- znorm per point ----
        if (tid < 128) {
            const float* zc = (const float*)s_z2;   // low half at 2*(c*128+pt)
            float zn = 0.f;
            #pragma unroll 8
            for (int c = 0; c < 64; c++) {
                float v = zc[(c * 128 + tid) * 2];
                zn = fmaf(v, v, zn);
            }
            s_zn[tid] = zn;
        }
        __syncthreads();

        // ---- Main sweep: 8 points x 8 codes per thread, 4 chunks ----
        float bestD[8]; int bestK[8];
        #pragma unroll
        for (int m = 0; m < 8; m++) { bestD[m] = 3.402823e38f; bestK[m] = 0; }
        float znm[8];
        #pragma unroll
        for (int m = 0; m < 8; m++) znm[m] = s_zn[pg * 8 + m];

        #pragma unroll
        for (int chunk = 0; chunk < 4; chunk++) {
            unsigned long long acc[8][4];
            #pragma unroll
            for (int m = 0; m < 8; m++)
                #pragma unroll
                for (int j = 0; j < 4; j++) acc[m][j] = 0ull;

            const unsigned long long* pc = s_cb + chunk * 64 + cg;
            const unsigned long long* pz = s_z2 + pg * 8;

            #pragma unroll 8
            for (int c = 0; c < 64; c++) {
                const ulonglong2* zrow = (const ulonglong2*)pz;
                ulonglong2 za = zrow[0], zb = zrow[1], zc2 = zrow[2], zd = zrow[3];
                unsigned long long z2r[8] = { za.x, za.y, zb.x, zb.y,
                                              zc2.x, zc2.y, zd.x, zd.y };
                unsigned long long cbp[4];
                #pragma unroll
                for (int j = 0; j < 4; j++) cbp[j] = pc[j * 16];
                #pragma unroll
                for (int m = 0; m < 8; m++)
                    #pragma unroll
                    for (int j = 0; j < 4; j++)
                        ffma2(acc[m][j], z2r[m], cbp[j]);
                pz += 128;        // next channel, z row
                pc += 256;        // next channel, cb row
            }
            // chunk epilogue: distances + running argmin (ascending code order)
            #pragma unroll
            for (int j = 0; j < 4; j++) {
                int pr = chunk * 64 + cg + j * 16;
                float2 en = unpk2(s_en[pr]);
                int k0 = 2 * pr;
                #pragma unroll
                for (int m = 0; m < 8; m++) {
                    float2 d = unpk2(acc[m][j]);
                    float dd = znm[m] + en.x - 2.f * d.x;
                    if (dd < bestD[m]) { bestD[m] = dd; bestK[m] = k0; }
                    dd = znm[m] + en.y - 2.f * d.y;
                    if (dd < bestD[m]) { bestD[m] = dd; bestK[m] = k0 + 1; }
                }
            }
        }

        // ---- Reduce across the 16 code-groups (tie -> lower k) ----
        #pragma unroll
        for (int m = 0; m < 8; m++) {
            float d = bestD[m]; int k = bestK[m];
            #pragma unroll
            for (int s = 1; s < 16; s <<= 1) {
                float od = __shfl_xor_sync(0xFFFFFFFFu, d, s);
                int   ok = __shfl_xor_sync(0xFFFFFFFFu, k, s);
                if (od < d || (od == d && ok < k)) { d = od; k = ok; }
            }
            if (cg == 0) s_idx[pg * 8 + m] = k;
        }
        __syncthreads();

        // ---- Emit ----
        if (mode == 2) {
            if (tid < 128) ((int*)out)[tile * 128 + tid] = s_idx[tid];
        } else {
            float4* out4 = (float4*)out + (size_t)tile * 2048;
            const float4* cb4 = (const float4*)cb;
            #pragma unroll
            for (int it = 0; it < 8; it++) {
                int i4 = it * 256 + tid;
                int p  = i4 >> 4;
                int c4 = i4 & 15;
                out4[i4] = cb4[(size_t)s_idx[p] * 16 + c4];
            }
            if (mode == 1 && tid < 128)
                out[ZQ_ELEMS + tile * 128 + tid] = (float)s_idx[tid];
        }
        // next iteration's first __syncthreads separates s_idx readers from rewriters
    }
}

extern "C" void kernel_launch(void* const* d_in, const int* in_sizes, int n_in,
                              void* d_out, int out_size)
{
    const float* z_e = (const float*)d_in[0];
    const float* cb  = (const float*)d_in[1];
    float* out = (float*)d_out;

    int mode;
    if (out_size >= ZQ_ELEMS + NPTS) mode = 1;
    else if (out_size >= ZQ_ELEMS)   mode = 0;
    else                             mode = 2;

    int sms = 0;
    cudaDeviceGetAttribute(&sms, cudaDevAttrMultiProcessorCount, 0);
    if (sms <= 0) sms = 148;

    cudaFuncSetAttribute(vq_kernel, cudaFuncAttributeMaxDynamicSharedMemorySize, SMEM_BYTES);
    vq_kernel<<<sms, 256, SMEM_BYTES>>>(z_e, cb, out, mode, sms);
}

// round 6
// speedup vs baseline: 1.0323x; 1.0323x over previous
#include <cuda_runtime.h>
#include <cstdint>

#define KCODES   512
#define DDIM     64
#define HWSZ     4096
#define NPTS     131072
#define TPTS     128            // points per tile
#define NTILES   (NPTS / TPTS)  // 1024
#define ZQ_ELEMS 8388608
#define NTHREADS 512

// dynamic SMEM layout (bytes):
//  s_cb : u64[64][256]  pair-transposed codebook {e[2p][c], e[2p+1][c]}  131072
//  s_z2 : u64[64][128]  duplicated z {v,v} per (channel, point)          65536
//  s_en : u64[256]      {||e_2p||^2, ||e_2p+1||^2}                       2048
//  s_zn : float[128]                                                     512
//  s_idx: int[128]                                                       512
#define OFF_CB   0
#define OFF_Z    131072
#define OFF_EN   (OFF_Z + 65536)
#define OFF_ZN   (OFF_EN + 2048)
#define OFF_IDX  (OFF_ZN + 512)
#define SMEM_BYTES (OFF_IDX + 512)   // 199680

__device__ __forceinline__ unsigned long long pk2(float lo, float hi) {
    unsigned long long r;
    asm("mov.b64 %0, {%1,%2};" : "=l"(r) : "f"(lo), "f"(hi));
    return r;
}
__device__ __forceinline__ float2 unpk2(unsigned long long v) {
    float2 f;
    asm("mov.b64 {%0,%1}, %2;" : "=f"(f.x), "=f"(f.y) : "l"(v));
    return f;
}
// packed dual-fp32 FMA (sm_100+; PTX-only, ptxas never auto-fuses)
__device__ __forceinline__ void ffma2(unsigned long long& d,
                                      unsigned long long a,
                                      unsigned long long b) {
    asm("fma.rn.f32x2 %0, %1, %2, %0;" : "+l"(d) : "l"(a), "l"(b));
}

// mode: 0 = z_q only; 1 = z_q + indices-as-float appended; 2 = indices only (int32)
__global__ void __launch_bounds__(NTHREADS, 1)
vq_kernel(const float* __restrict__ z_e,
          const float* __restrict__ cb,
          float* __restrict__ out,
          int mode, int nctas)
{
    extern __shared__ char smem[];
    unsigned long long* s_cb = (unsigned long long*)(smem + OFF_CB);
    unsigned long long* s_z2 = (unsigned long long*)(smem + OFF_Z);
    unsigned long long* s_en = (unsigned long long*)(smem + OFF_EN);
    float* s_zn  = (float*)(smem + OFF_ZN);
    int*   s_idx = (int*)  (smem + OFF_IDX);

    const int tid = threadIdx.x;
    const int cg  = tid & 15;    // code group (16)
    const int pg  = tid >> 4;    // point group (32): points pg*4 .. pg*4+3

    // ---- Stage codebook once: pair-transposed + per-code norms (1 code/thread) ----
    {
        const int code = tid;                       // 0..511
        const float4* e0 = (const float4*)(cb + (size_t)code * DDIM);
        float* s_cbf = (float*)s_cb;
        float* s_enf = (float*)s_en;
        const int p    = code >> 1;
        const int half = code & 1;                  // lo = even code, hi = odd
        float nrm = 0.f;
        #pragma unroll
        for (int c4 = 0; c4 < 16; c4++) {
            float4 a = e0[c4];
            nrm += a.x*a.x + a.y*a.y + a.z*a.z + a.w*a.w;
            int c = 4 * c4;
            s_cbf[((c+0)*256 + p)*2 + half] = a.x;
            s_cbf[((c+1)*256 + p)*2 + half] = a.y;
            s_cbf[((c+2)*256 + p)*2 + half] = a.z;
            s_cbf[((c+3)*256 + p)*2 + half] = a.w;
        }
        s_enf[code] = nrm;
    }

    for (int tile = blockIdx.x; tile < NTILES; tile += nctas) {
        // ---- Stage z tile, duplicated {v,v}. Tile never straddles batch b. ----
        {
            const float* zg = z_e + (size_t)(tile >> 5) * (DDIM * HWSZ)
                                  + (size_t)(tile & 31) * TPTS;
            #pragma unroll
            for (int it = 0; it < 4; it++) {
                int i4 = it * NTHREADS + tid;   // 0..2047 float4 slots
                int c  = i4 >> 5;               // channel
                int p  = (i4 & 31) * 4;         // point base
                float4 v = *(const float4*)(zg + (size_t)c * HWSZ + p);
                ulonglong2* dst = (ulonglong2*)(s_z2 + c * 128 + p);
                dst[0] = make_ulonglong2(pk2(v.x, v.x), pk2(v.y, v.y));
                dst[1] = make_ulonglong2(pk2(v.z, v.z), pk2(v.w, v.w));
            }
        }
        __syncthreads();

        // ---- znorm per point ----
        if (tid < 128) {
            const float* zc = (const float*)s_z2;   // low half at 2*(c*128+pt)
            float zn = 0.f;
            #pragma unroll 8
            for (int c = 0; c < 64; c++) {
                float v = zc[(c * 128 + tid) * 2];
                zn = fmaf(v, v, zn);
            }
            s_zn[tid] = zn;
        }
        __syncthreads();

        // ---- Main sweep: 4 points x 8 pairs per thread, 2 chunks of 128 pairs ----
        float bestD[4]; int bestK[4];
        #pragma unroll
        for (int m = 0; m < 4; m++) { bestD[m] = 3.402823e38f; bestK[m] = 0; }
        float znm[4];
        #pragma unroll
        for (int m = 0; m < 4; m++) znm[m] = s_zn[pg * 4 + m];

        #pragma unroll
        for (int chunk = 0; chunk < 2; chunk++) {
            unsigned long long acc[4][8];
            #pragma unroll
            for (int m = 0; m < 4; m++)
                #pragma unroll
                for (int j = 0; j < 8; j++) acc[m][j] = 0ull;

            const unsigned long long* pc = s_cb + chunk * 128 + cg;
            const unsigned long long* pz = s_z2 + pg * 4;

            #pragma unroll 8
            for (int c = 0; c < 64; c++) {
                const ulonglong2* zrow = (const ulonglong2*)pz;
                ulonglong2 za = zrow[0], zb = zrow[1];
                unsigned long long z2r[4] = { za.x, za.y, zb.x, zb.y };
                unsigned long long cbp[4];
                #pragma unroll
                for (int j = 0; j < 4; j++) cbp[j] = pc[j * 16];
                #pragma unroll
                for (int m = 0; m < 4; m++)
                    #pragma unroll
                    for (int j = 0; j < 4; j++)
                        ffma2(acc[m][j], z2r[m], cbp[j]);
                #pragma unroll
                for (int j = 0; j < 4; j++) cbp[j] = pc[(j + 4) * 16];
                #pragma unroll
                for (int m = 0; m < 4; m++)
                    #pragma unroll
                    for (int j = 0; j < 4; j++)
                        ffma2(acc[m][j + 4], z2r[m], cbp[j]);
                pz += 128;        // next channel, z row
                pc += 256;        // next channel, cb row
            }
            // chunk epilogue: distances + running argmin (ascending code order)
            #pragma unroll
            for (int j = 0; j < 8; j++) {
                int pr = chunk * 128 + j * 16 + cg;
                float2 en = unpk2(s_en[pr]);
                int k0 = 2 * pr;
                #pragma unroll
                for (int m = 0; m < 4; m++) {
                    float2 d = unpk2(acc[m][j]);
                    float dd = znm[m] + en.x - 2.f * d.x;
                    if (dd < bestD[m]) { bestD[m] = dd; bestK[m] = k0; }
                    dd = znm[m] + en.y - 2.f * d.y;
                    if (dd < bestD[m]) { bestD[m] = dd; bestK[m] = k0 + 1; }
                }
            }
        }

        // ---- Reduce across the 16 code-groups (tie -> lower k) ----
        #pragma unroll
        for (int m = 0; m < 4; m++) {
            float d = bestD[m]; int k = bestK[m];
            #pragma unroll
            for (int s = 1; s < 16; s <<= 1) {
                float od = __shfl_xor_sync(0xFFFFFFFFu, d, s);
                int   ok = __shfl_xor_sync(0xFFFFFFFFu, k, s);
                if (od < d || (od == d && ok < k)) { d = od; k = ok; }
            }
            if (cg == 0) s_idx[pg * 4 + m] = k;
        }
        __syncthreads();

        // ---- Emit ----
        if (mode == 2) {
            if (tid < 128) ((int*)out)[tile * 128 + tid] = s_idx[tid];
        } else {
            float4* out4 = (float4*)out + (size_t)tile * 2048;
            const float4* cb4 = (const float4*)cb;
            #pragma unroll
            for (int it = 0; it < 4; it++) {
                int i4 = it * NTHREADS + tid;
                int p  = i4 >> 4;
                int c4 = i4 & 15;
                out4[i4] = cb4[(size_t)s_idx[p] * 16 + c4];
            }
            if (mode == 1 && tid < 128)
                out[ZQ_ELEMS + tile * 128 + tid] = (float)s_idx[tid];
        }
        // next iteration's first __syncthreads separates s_idx readers from rewriters
    }
}

extern "C" void kernel_launch(void* const* d_in, const int* in_sizes, int n_in,
                              void* d_out, int out_size)
{
    const float* z_e = (const float*)d_in[0];
    const float* cb  = (const float*)d_in[1];
    float* out = (float*)d_out;

    int mode;
    if (out_size >= ZQ_ELEMS + NPTS) mode = 1;
    else if (out_size >= ZQ_ELEMS)   mode = 0;
    else                             mode = 2;

    int sms = 0;
    cudaDeviceGetAttribute(&sms, cudaDevAttrMultiProcessorCount, 0);
    if (sms <= 0) sms = 148;

    cudaFuncSetAttribute(vq_kernel, cudaFuncAttributeMaxDynamicSharedMemorySize, SMEM_BYTES);
    vq_kernel<<<sms, NTHREADS, SMEM_BYTES>>>(z_e, cb, out, mode, sms);
}